// round 10
// baseline (speedup 1.0000x reference)
#include <cuda_runtime.h>
#include <math.h>
#include <stdint.h>

#define B  4
#define NN 65536
#define KK 16
#define DD 32
#define NP 16384

// scratch
__device__ float  g_pool_t[(size_t)B * NN * DD];    // 33.6 MB  [b][n][d]
__device__ float  g_interp_t[(size_t)B * NP * DD];  //  8.4 MB  [b][np][d]
__device__ float4 g_xyz4[(size_t)B * NN];           //  4.2 MB  padded xyz

#define TB1  (B * (NN / 32))       // 8192  transpose feat_pool tiles
#define TB2  (B * (NP / 32))       // 2048  transpose feat_interp tiles
#define XB   (B * NN / 256)        // 1024  xyz padding blocks
#define K0B  (TB1 + TB2 + XB)      // 11264

#define RELB  (B * NN * KK / 512)  // 8192  rel blocks (512 pairs each)
#define POOLB (B * (NP / 32))      // 2048  pool blocks
#define IB4   (B * (NN / 128))     // 2048  interp blocks (4 tiles each)
#define K1B   (RELB + POOLB + IB4) // 12288, dispatched bid%6 (rel gets 4/6)

__device__ __forceinline__ uint32_t smem_u32(const void* p) {
    uint32_t a;
    asm("{ .reg .u64 t; cvta.to.shared.u64 t, %1; cvt.u32.u64 %0, t; }"
        : "=r"(a) : "l"(p));
    return a;
}

// ============ K0: xyz padding + both transposes ============
__global__ void __launch_bounds__(256) kernel0(
    const float* __restrict__ xyz,
    const float* __restrict__ feat_pool,
    const float* __restrict__ feat_interp)
{
    __shared__ float sm[32 * 33];
    int bid = blockIdx.x;
    int tid = threadIdx.x;

    if (bid < XB) {
        // pad xyz [B*N,3] -> [B*N] float4
        float* s = sm;   // needs 768 floats
        int p0 = bid * 256;
        const float* src = xyz + (size_t)p0 * 3;
        s[tid]       = __ldcs(&src[tid]);
        s[256 + tid] = __ldcs(&src[256 + tid]);
        s[512 + tid] = __ldcs(&src[512 + tid]);
        __syncthreads();
        g_xyz4[p0 + tid] = make_float4(s[tid * 3], s[tid * 3 + 1], s[tid * 3 + 2], 0.0f);
    } else {
        // transpose [B,32,M] -> [B,M,32]
        float (*tile)[33] = (float (*)[33])sm;
        int tb = bid - XB;
        const float* in;
        float* outp;
        int M;
        if (tb < TB1) { in = feat_pool;   outp = g_pool_t;   M = NN; }
        else          { in = feat_interp; outp = g_interp_t; M = NP; tb -= TB1; }
        int mb = M / 32;
        int b  = tb / mb;
        int m0 = (tb - b * mb) * 32;
        int tx = tid & 31, ty = tid >> 5;
#pragma unroll
        for (int rr = 0; rr < 4; rr++) {
            int d = ty + 8 * rr;
            tile[d][tx] = __ldcs(&in[((size_t)(b * DD + d)) * M + m0 + tx]);
        }
        __syncthreads();
#pragma unroll
        for (int rr = 0; rr < 4; rr++) {
            int m = ty + 8 * rr;
            outp[((size_t)(b * M + m0 + m)) * DD + tx] = tile[tx][m];
        }
    }
}

// ============ K1: rel (TMA bulk store) + pool + interp, bid%6 ============
__global__ void __launch_bounds__(256, 7) kernel1(
    const int* __restrict__ nidx,
    const int* __restrict__ pool_idx,
    const int* __restrict__ interp_idx,
    float* __restrict__ out_rel,
    float* __restrict__ out_pool,
    float* __restrict__ out_interp)
{
    __shared__ __align__(16) float smem[5120];   // 20 KB
    int bid = blockIdx.x;
    int tid = threadIdx.x;
    int r = bid % 6;
    int g = bid / 6;

    if (r == 0) {
        // -------- gather-max pooling --------
        float (*tile)[33] = (float (*)[33])smem;
        int lane = tid & 31, w = tid >> 5;
        int row  = w * 4 + (lane >> 3);
        int dv   = lane & 7;
        int b   = g / (NP / 32);
        int np0 = (g - b * (NP / 32)) * 32;
        const int* ip = pool_idx + (b * NP + np0 + row) * KK;
        const float* basep = g_pool_t + (size_t)b * NN * DD;

        float4 m = make_float4(-INFINITY, -INFINITY, -INFINITY, -INFINITY);
#pragma unroll
        for (int kc = 0; kc < 4; kc++) {
            int4 q = __ldcs((const int4*)ip + kc);
            int qq[4] = {q.x, q.y, q.z, q.w};
#pragma unroll
            for (int j = 0; j < 4; j++) {
                float4 v = *(const float4*)(basep + qq[j] * DD + dv * 4);
                m.x = fmaxf(m.x, v.x); m.y = fmaxf(m.y, v.y);
                m.z = fmaxf(m.z, v.z); m.w = fmaxf(m.w, v.w);
            }
        }
        tile[row][dv * 4 + 0] = m.x;
        tile[row][dv * 4 + 1] = m.y;
        tile[row][dv * 4 + 2] = m.z;
        tile[row][dv * 4 + 3] = m.w;
        __syncthreads();
#pragma unroll
        for (int rr = 0; rr < 4; rr++) {
            int d = w + 8 * rr;
            __stcs(&out_pool[(size_t)(b * DD + d) * NP + np0 + lane], tile[lane][d]);
        }
    } else if (r == 3) {
        // -------- nearest interpolation: 4 tiles / block --------
        float (*tile)[33] = (float (*)[33])smem;
        int lane = tid & 31, w = tid >> 5;
        int row  = w * 4 + (lane >> 3);
        int dv   = lane & 7;
        int b  = g / (NN / 128);
        int u0 = (g - b * (NN / 128)) * 128;

        float4 v[4];
#pragma unroll
        for (int it = 0; it < 4; it++) {
            int i = __ldg(&interp_idx[b * NN + u0 + it * 32 + row]);
            v[it] = *(const float4*)(g_interp_t + ((size_t)(b * NP + i)) * DD + dv * 4);
        }
#pragma unroll
        for (int it = 0; it < 4; it++) {
            tile[it * 32 + row][dv * 4 + 0] = v[it].x;
            tile[it * 32 + row][dv * 4 + 1] = v[it].y;
            tile[it * 32 + row][dv * 4 + 2] = v[it].z;
            tile[it * 32 + row][dv * 4 + 3] = v[it].w;
        }
        __syncthreads();
#pragma unroll
        for (int it = 0; it < 4; it++) {
#pragma unroll
            for (int rr = 0; rr < 4; rr++) {
                int d = w + 8 * rr;
                __stcs(&out_interp[(size_t)(b * DD + d) * NN + u0 + it * 32 + lane],
                       tile[it * 32 + lane][d]);
            }
        }
    } else {
        // -------- rel: 512 pairs / block, 2 pairs / thread, TMA bulk store --------
        // r in {1,2,4,5} -> sub 0..3
        int sub = (r < 3) ? (r - 1) : (r - 2);
        int rb = g * 4 + sub;               // 0..8191
        int pbase = rb * 512;
        int b   = pbase >> 20;              // N*K = 2^20
        int bb  = b << 16;
        int nkb = pbase & 0xFFFFF;
        int t2  = tid * 2;

        int2 ii = __ldcs((const int2*)(nidx + pbase + t2));
        float4 Q0 = __ldg(&g_xyz4[bb + ii.x]);
        float4 Q1 = __ldg(&g_xyz4[bb + ii.y]);
        // pairs (2t, 2t+1) share n since t2 is even and K=16
        float4 P  = __ldg(&g_xyz4[bb + ((nkb + t2) >> 4)]);

        float rx0 = P.x - Q0.x, ry0 = P.y - Q0.y, rz0 = P.z - Q0.z;
        float d0 = sqrtf(rx0 * rx0 + ry0 * ry0 + rz0 * rz0);
        float rx1 = P.x - Q1.x, ry1 = P.y - Q1.y, rz1 = P.z - Q1.z;
        float d1 = sqrtf(rx1 * rx1 + ry1 * ry1 + rz1 * rz1);

        float4* sp = (float4*)(smem + tid * 20);
        sp[0] = make_float4(d0, rx0, ry0, rz0);
        sp[1] = make_float4(P.x, P.y, P.z, Q0.x);
        sp[2] = make_float4(Q0.y, Q0.z, d1, rx1);
        sp[3] = make_float4(ry1, rz1, P.x, P.y);
        sp[4] = make_float4(P.z, Q1.x, Q1.y, Q1.z);
        __syncthreads();

        // one bulk S2G copy of the whole 20 KB chunk (contiguous in out_rel)
        asm volatile("fence.proxy.async.shared::cta;" ::: "memory");
        if (tid == 0) {
            uint32_t sa = smem_u32(smem);
            float* gp = out_rel + (size_t)rb * 5120;
            asm volatile(
                "cp.async.bulk.global.shared::cta.bulk_group [%0], [%1], %2;"
                :: "l"(gp), "r"(sa), "n"(20480) : "memory");
            asm volatile("cp.async.bulk.commit_group;" ::: "memory");
            asm volatile("cp.async.bulk.wait_group.read 0;" ::: "memory");
        }
        __syncthreads();
    }
}

extern "C" void kernel_launch(void* const* d_in, const int* in_sizes, int n_in,
                              void* d_out, int out_size) {
    const float* xyz         = (const float*)d_in[0];   // [B,N,3]
    const int*   neigh_idx   = (const int*)  d_in[1];   // [B,N,K]
    const float* feat_pool   = (const float*)d_in[2];   // [B,32,N,1]
    const int*   pool_idx    = (const int*)  d_in[3];   // [B,Np,K]
    const float* feat_interp = (const float*)d_in[4];   // [B,32,Np,1]
    const int*   interp_idx  = (const int*)  d_in[5];   // [B,N,1]

    float* out = (float*)d_out;
    float* out_rel    = out;                                // B*N*K*10
    float* out_pool   = out + (size_t)B * NN * KK * 10;     // B*32*Np
    float* out_interp = out_pool + (size_t)B * DD * NP;     // B*32*N

    kernel0<<<K0B, 256>>>(xyz, feat_pool, feat_interp);
    kernel1<<<K1B, 256>>>(neigh_idx, pool_idx, interp_idx,
                          out_rel, out_pool, out_interp);
}

// round 11
// speedup vs baseline: 1.0049x; 1.0049x over previous
#include <cuda_runtime.h>
#include <math.h>
#include <stdint.h>

#define B  4
#define NN 65536
#define KK 16
#define DD 32
#define NP 16384

// scratch
__device__ float  g_pool_t[(size_t)B * NN * DD];    // 33.6 MB  [b][n][d]
__device__ float  g_interp_t[(size_t)B * NP * DD];  //  8.4 MB  [b][np][d]
__device__ float4 g_xyz4[(size_t)B * NN];           //  4.2 MB  padded xyz

#define TB1  (B * (NN / 32))       // 8192  transpose feat_pool tiles
#define TB2  (B * (NP / 32))       // 2048  transpose feat_interp tiles
#define XB   (B * NN / 256)        // 1024  xyz padding blocks
#define K0B  (TB1 + TB2 + XB)      // 11264

#define RELB  (B * NN * KK / 512)  // 8192  rel blocks (512 pairs each)
#define POOLB (B * (NP / 32))      // 2048  pool blocks
#define IB4   (B * (NN / 128))     // 2048  interp blocks (4 tiles each)
#define K1B   (RELB + POOLB + IB4) // 12288, dispatched bid%6 (rel gets 4/6)

__device__ __forceinline__ uint32_t smem_u32(const void* p) {
    uint32_t a;
    asm("{ .reg .u64 t; cvta.to.shared.u64 t, %1; cvt.u32.u64 %0, t; }"
        : "=r"(a) : "l"(p));
    return a;
}

// ============ K0: xyz padding + both transposes ============
__global__ void __launch_bounds__(256) kernel0(
    const float* __restrict__ xyz,
    const float* __restrict__ feat_pool,
    const float* __restrict__ feat_interp)
{
    __shared__ float sm[32 * 33];
    int bid = blockIdx.x;
    int tid = threadIdx.x;

    if (bid < XB) {
        // pad xyz [B*N,3] -> [B*N] float4
        float* s = sm;   // needs 768 floats
        int p0 = bid * 256;
        const float* src = xyz + (size_t)p0 * 3;
        s[tid]       = __ldcs(&src[tid]);
        s[256 + tid] = __ldcs(&src[256 + tid]);
        s[512 + tid] = __ldcs(&src[512 + tid]);
        __syncthreads();
        g_xyz4[p0 + tid] = make_float4(s[tid * 3], s[tid * 3 + 1], s[tid * 3 + 2], 0.0f);
    } else {
        // transpose [B,32,M] -> [B,M,32]
        float (*tile)[33] = (float (*)[33])sm;
        int tb = bid - XB;
        const float* in;
        float* outp;
        int M;
        if (tb < TB1) { in = feat_pool;   outp = g_pool_t;   M = NN; }
        else          { in = feat_interp; outp = g_interp_t; M = NP; tb -= TB1; }
        int mb = M / 32;
        int b  = tb / mb;
        int m0 = (tb - b * mb) * 32;
        int tx = tid & 31, ty = tid >> 5;
#pragma unroll
        for (int rr = 0; rr < 4; rr++) {
            int d = ty + 8 * rr;
            tile[d][tx] = __ldcs(&in[((size_t)(b * DD + d)) * M + m0 + tx]);
        }
        __syncthreads();
        // vectorized store side: thread (m = tid>>3, c = tid&7) -> one float4
        {
            int m = tid >> 3;
            int c = tid & 7;
            float4 v = make_float4(tile[4 * c + 0][m], tile[4 * c + 1][m],
                                   tile[4 * c + 2][m], tile[4 * c + 3][m]);
            float4* o4 = (float4*)(outp + ((size_t)(b * M + m0)) * DD);
            o4[tid] = v;       // = o4[m*8 + c], rows of 32 floats contiguous
        }
    }
}

// ============ K1: rel (warp-autonomous TMA) + pool + interp, bid%6 ============
__global__ void __launch_bounds__(256) kernel1(
    const int* __restrict__ nidx,
    const int* __restrict__ pool_idx,
    const int* __restrict__ interp_idx,
    float* __restrict__ out_rel,
    float* __restrict__ out_pool,
    float* __restrict__ out_interp)
{
    __shared__ __align__(16) float smem[5120];   // 20 KB
    int bid = blockIdx.x;
    int tid = threadIdx.x;
    int r = bid % 6;
    int g = bid / 6;

    if (r == 0) {
        // -------- gather-max pooling --------
        float (*tile)[33] = (float (*)[33])smem;
        int lane = tid & 31, w = tid >> 5;
        int row  = w * 4 + (lane >> 3);
        int dv   = lane & 7;
        int b   = g / (NP / 32);
        int np0 = (g - b * (NP / 32)) * 32;
        const int* ip = pool_idx + (b * NP + np0 + row) * KK;
        const float* basep = g_pool_t + (size_t)b * NN * DD;

        float4 m = make_float4(-INFINITY, -INFINITY, -INFINITY, -INFINITY);
#pragma unroll
        for (int kc = 0; kc < 4; kc++) {
            int4 q = __ldcs((const int4*)ip + kc);
            int qq[4] = {q.x, q.y, q.z, q.w};
#pragma unroll
            for (int j = 0; j < 4; j++) {
                float4 v = *(const float4*)(basep + qq[j] * DD + dv * 4);
                m.x = fmaxf(m.x, v.x); m.y = fmaxf(m.y, v.y);
                m.z = fmaxf(m.z, v.z); m.w = fmaxf(m.w, v.w);
            }
        }
        tile[row][dv * 4 + 0] = m.x;
        tile[row][dv * 4 + 1] = m.y;
        tile[row][dv * 4 + 2] = m.z;
        tile[row][dv * 4 + 3] = m.w;
        __syncthreads();
#pragma unroll
        for (int rr = 0; rr < 4; rr++) {
            int d = w + 8 * rr;
            __stcs(&out_pool[(size_t)(b * DD + d) * NP + np0 + lane], tile[lane][d]);
        }
    } else if (r == 3) {
        // -------- nearest interpolation: 4 tiles / block --------
        float (*tile)[33] = (float (*)[33])smem;
        int lane = tid & 31, w = tid >> 5;
        int row  = w * 4 + (lane >> 3);
        int dv   = lane & 7;
        int b  = g / (NN / 128);
        int u0 = (g - b * (NN / 128)) * 128;

        float4 v[4];
#pragma unroll
        for (int it = 0; it < 4; it++) {
            int i = __ldg(&interp_idx[b * NN + u0 + it * 32 + row]);
            v[it] = *(const float4*)(g_interp_t + ((size_t)(b * NP + i)) * DD + dv * 4);
        }
#pragma unroll
        for (int it = 0; it < 4; it++) {
            tile[it * 32 + row][dv * 4 + 0] = v[it].x;
            tile[it * 32 + row][dv * 4 + 1] = v[it].y;
            tile[it * 32 + row][dv * 4 + 2] = v[it].z;
            tile[it * 32 + row][dv * 4 + 3] = v[it].w;
        }
        __syncthreads();
#pragma unroll
        for (int it = 0; it < 4; it++) {
#pragma unroll
            for (int rr = 0; rr < 4; rr++) {
                int d = w + 8 * rr;
                __stcs(&out_interp[(size_t)(b * DD + d) * NN + u0 + it * 32 + lane],
                       tile[it * 32 + lane][d]);
            }
        }
    } else {
        // -------- rel: 512 pairs / block, warp-autonomous TMA --------
        // r in {1,2,4,5} -> sub 0..3
        int sub = (r < 3) ? (r - 1) : (r - 2);
        int rb = g * 4 + sub;               // 0..8191
        int lane = tid & 31, w = tid >> 5;
        int pbase = rb * 512 + w * 64;      // this warp's 64 pairs
        int b   = pbase >> 20;              // N*K = 2^20
        int bb  = b << 16;
        int nkb = pbase & 0xFFFFF;
        int t2  = lane * 2;

        int2 ii = __ldcs((const int2*)(nidx + pbase + t2));
        float4 Q0 = __ldg(&g_xyz4[bb + ii.x]);
        float4 Q1 = __ldg(&g_xyz4[bb + ii.y]);
        // pairs (2t, 2t+1) share n since (pbase + t2) is even and K=16
        float4 P  = __ldg(&g_xyz4[bb + ((nkb + t2) >> 4)]);

        float rx0 = P.x - Q0.x, ry0 = P.y - Q0.y, rz0 = P.z - Q0.z;
        float d0 = sqrtf(rx0 * rx0 + ry0 * ry0 + rz0 * rz0);
        float rx1 = P.x - Q1.x, ry1 = P.y - Q1.y, rz1 = P.z - Q1.z;
        float d1 = sqrtf(rx1 * rx1 + ry1 * ry1 + rz1 * rz1);

        float* ws = smem + w * 640;          // warp's 2560B staging slice
        float4* sp = (float4*)(ws + lane * 20);
        sp[0] = make_float4(d0, rx0, ry0, rz0);
        sp[1] = make_float4(P.x, P.y, P.z, Q0.x);
        sp[2] = make_float4(Q0.y, Q0.z, d1, rx1);
        sp[3] = make_float4(ry1, rz1, P.x, P.y);
        sp[4] = make_float4(P.z, Q1.x, Q1.y, Q1.z);
        __syncwarp();
        asm volatile("fence.proxy.async.shared::cta;" ::: "memory");
        if (lane == 0) {
            uint32_t sa = smem_u32(ws);
            float* gp = out_rel + (size_t)rb * 5120 + w * 640;
            asm volatile(
                "cp.async.bulk.global.shared::cta.bulk_group [%0], [%1], %2;"
                :: "l"(gp), "r"(sa), "n"(2560) : "memory");
            asm volatile("cp.async.bulk.commit_group;" ::: "memory");
            asm volatile("cp.async.bulk.wait_group.read 0;" ::: "memory");
        }
        __syncwarp();
    }
}

extern "C" void kernel_launch(void* const* d_in, const int* in_sizes, int n_in,
                              void* d_out, int out_size) {
    const float* xyz         = (const float*)d_in[0];   // [B,N,3]
    const int*   neigh_idx   = (const int*)  d_in[1];   // [B,N,K]
    const float* feat_pool   = (const float*)d_in[2];   // [B,32,N,1]
    const int*   pool_idx    = (const int*)  d_in[3];   // [B,Np,K]
    const float* feat_interp = (const float*)d_in[4];   // [B,32,Np,1]
    const int*   interp_idx  = (const int*)  d_in[5];   // [B,N,1]

    float* out = (float*)d_out;
    float* out_rel    = out;                                // B*N*K*10
    float* out_pool   = out + (size_t)B * NN * KK * 10;     // B*32*Np
    float* out_interp = out_pool + (size_t)B * DD * NP;     // B*32*N

    kernel0<<<K0B, 256>>>(xyz, feat_pool, feat_interp);
    kernel1<<<K1B, 256>>>(neigh_idx, pool_idx, interp_idx,
                          out_rel, out_pool, out_interp);
}

// round 12
// speedup vs baseline: 1.0607x; 1.0555x over previous
#include <cuda_runtime.h>
#include <math.h>
#include <stdint.h>

#define B  4
#define NN 65536
#define KK 16
#define DD 32
#define NP 16384

// scratch
__device__ float  g_pool_t[(size_t)B * NN * DD];    // 33.6 MB  [b][n][d]
__device__ float  g_interp_t[(size_t)B * NP * DD];  //  8.4 MB  [b][np][d]
__device__ float4 g_xyz4[(size_t)B * NN];           //  4.2 MB  padded xyz

#define TB1   (B * (NN / 32))      // 8192  transpose feat_pool tiles
#define TB2   (B * (NP / 32))      // 2048  transpose feat_interp tiles
#define XB    (B * NN / 256)       // 1024  xyz padding blocks
#define RELB  (B * NN * KK / 512)  // 8192  rel blocks (512 pairs each)
#define POOLB (B * (NP / 32))      // 2048  pool blocks
#define IB4   (B * (NN / 128))     // 2048  interp blocks (4 tiles each)

__device__ __forceinline__ uint32_t smem_u32(const void* p) {
    uint32_t a;
    asm("{ .reg .u64 t; cvta.to.shared.u64 t, %1; cvt.u32.u64 %0, t; }"
        : "=r"(a) : "l"(p));
    return a;
}

// ============ kX: pad xyz [B*N,3] -> float4 ============
__global__ void __launch_bounds__(256) kX(const float* __restrict__ xyz) {
    __shared__ float s[768];
    int tid = threadIdx.x;
    int p0 = blockIdx.x * 256;
    const float* src = xyz + (size_t)p0 * 3;
    s[tid]       = __ldcs(&src[tid]);
    s[256 + tid] = __ldcs(&src[256 + tid]);
    s[512 + tid] = __ldcs(&src[512 + tid]);
    __syncthreads();
    g_xyz4[p0 + tid] = make_float4(s[tid * 3], s[tid * 3 + 1], s[tid * 3 + 2], 0.0f);
}

// ============ kT: transposes [B,32,M] -> [B,M,32] ============
__global__ void __launch_bounds__(256) kT(
    const float* __restrict__ feat_pool,
    const float* __restrict__ feat_interp)
{
    __shared__ float sm[32 * 33];
    float (*tile)[33] = (float (*)[33])sm;
    int tid = threadIdx.x;
    int tb = blockIdx.x;
    const float* in;
    float* outp;
    int M;
    if (tb < TB1) { in = feat_pool;   outp = g_pool_t;   M = NN; }
    else          { in = feat_interp; outp = g_interp_t; M = NP; tb -= TB1; }
    int mb = M / 32;
    int b  = tb / mb;
    int m0 = (tb - b * mb) * 32;
    int tx = tid & 31, ty = tid >> 5;
#pragma unroll
    for (int rr = 0; rr < 4; rr++) {
        int d = ty + 8 * rr;
        tile[d][tx] = __ldcs(&in[((size_t)(b * DD + d)) * M + m0 + tx]);
    }
    __syncthreads();
    // vectorized store: thread (m = tid>>3, c = tid&7) -> one float4
    int m = tid >> 3;
    int c = tid & 7;
    float4 v = make_float4(tile[4 * c + 0][m], tile[4 * c + 1][m],
                           tile[4 * c + 2][m], tile[4 * c + 3][m]);
    float4* o4 = (float4*)(outp + ((size_t)(b * M + m0)) * DD);
    o4[tid] = v;
}

// ============ kRel: 512 pairs/block, 2 pairs/thread, TMA bulk store ============
__global__ void __launch_bounds__(256) kRel(
    const int* __restrict__ nidx,
    float* __restrict__ out_rel)
{
    __shared__ __align__(16) float smem[5120];   // 20 KB
    int tid = threadIdx.x;
    int rb = blockIdx.x;                // 0..8191
    int pbase = rb * 512;
    int b   = pbase >> 20;              // N*K = 2^20
    int bb  = b << 16;
    int nkb = pbase & 0xFFFFF;
    int t2  = tid * 2;

    int2 ii = __ldcs((const int2*)(nidx + pbase + t2));
    float4 Q0 = __ldg(&g_xyz4[bb + ii.x]);
    float4 Q1 = __ldg(&g_xyz4[bb + ii.y]);
    // pairs (2t, 2t+1) share n since t2 is even and K=16
    float4 P  = __ldg(&g_xyz4[bb + ((nkb + t2) >> 4)]);

    float rx0 = P.x - Q0.x, ry0 = P.y - Q0.y, rz0 = P.z - Q0.z;
    float d0 = sqrtf(rx0 * rx0 + ry0 * ry0 + rz0 * rz0);
    float rx1 = P.x - Q1.x, ry1 = P.y - Q1.y, rz1 = P.z - Q1.z;
    float d1 = sqrtf(rx1 * rx1 + ry1 * ry1 + rz1 * rz1);

    float4* sp = (float4*)(smem + tid * 20);
    sp[0] = make_float4(d0, rx0, ry0, rz0);
    sp[1] = make_float4(P.x, P.y, P.z, Q0.x);
    sp[2] = make_float4(Q0.y, Q0.z, d1, rx1);
    sp[3] = make_float4(ry1, rz1, P.x, P.y);
    sp[4] = make_float4(P.z, Q1.x, Q1.y, Q1.z);
    __syncthreads();

    asm volatile("fence.proxy.async.shared::cta;" ::: "memory");
    if (tid == 0) {
        uint32_t sa = smem_u32(smem);
        float* gp = out_rel + (size_t)rb * 5120;
        asm volatile(
            "cp.async.bulk.global.shared::cta.bulk_group [%0], [%1], %2;"
            :: "l"(gp), "r"(sa), "n"(20480) : "memory");
        asm volatile("cp.async.bulk.commit_group;" ::: "memory");
        asm volatile("cp.async.bulk.wait_group.read 0;" ::: "memory");
    }
    __syncthreads();
}

// ============ kPI: pool + interp (bid&1) ============
__global__ void __launch_bounds__(256) kPI(
    const int* __restrict__ pool_idx,
    const int* __restrict__ interp_idx,
    float* __restrict__ out_pool,
    float* __restrict__ out_interp)
{
    __shared__ float smem[4 * 32 * 33];
    int bid = blockIdx.x;
    int tid = threadIdx.x;
    int lane = tid & 31, w = tid >> 5;
    int row  = w * 4 + (lane >> 3);
    int dv   = lane & 7;
    int r = bid & 1;
    int g = bid >> 1;

    if (r == 0) {
        // -------- gather-max pooling --------
        float (*tile)[33] = (float (*)[33])smem;
        int b   = g / (NP / 32);
        int np0 = (g - b * (NP / 32)) * 32;
        const int* ip = pool_idx + (b * NP + np0 + row) * KK;
        const float* basep = g_pool_t + (size_t)b * NN * DD;

        float4 m = make_float4(-INFINITY, -INFINITY, -INFINITY, -INFINITY);
#pragma unroll
        for (int kc = 0; kc < 4; kc++) {
            int4 q = __ldcs((const int4*)ip + kc);
            int qq[4] = {q.x, q.y, q.z, q.w};
#pragma unroll
            for (int j = 0; j < 4; j++) {
                float4 v = *(const float4*)(basep + qq[j] * DD + dv * 4);
                m.x = fmaxf(m.x, v.x); m.y = fmaxf(m.y, v.y);
                m.z = fmaxf(m.z, v.z); m.w = fmaxf(m.w, v.w);
            }
        }
        tile[row][dv * 4 + 0] = m.x;
        tile[row][dv * 4 + 1] = m.y;
        tile[row][dv * 4 + 2] = m.z;
        tile[row][dv * 4 + 3] = m.w;
        __syncthreads();
#pragma unroll
        for (int rr = 0; rr < 4; rr++) {
            int d = w + 8 * rr;
            __stcs(&out_pool[(size_t)(b * DD + d) * NP + np0 + lane], tile[lane][d]);
        }
    } else {
        // -------- nearest interpolation: 4 tiles / block --------
        float (*tile)[33] = (float (*)[33])smem;
        int b  = g / (NN / 128);
        int u0 = (g - b * (NN / 128)) * 128;

        float4 v[4];
#pragma unroll
        for (int it = 0; it < 4; it++) {
            int i = __ldg(&interp_idx[b * NN + u0 + it * 32 + row]);
            v[it] = *(const float4*)(g_interp_t + ((size_t)(b * NP + i)) * DD + dv * 4);
        }
#pragma unroll
        for (int it = 0; it < 4; it++) {
            tile[it * 32 + row][dv * 4 + 0] = v[it].x;
            tile[it * 32 + row][dv * 4 + 1] = v[it].y;
            tile[it * 32 + row][dv * 4 + 2] = v[it].z;
            tile[it * 32 + row][dv * 4 + 3] = v[it].w;
        }
        __syncthreads();
#pragma unroll
        for (int it = 0; it < 4; it++) {
#pragma unroll
            for (int rr = 0; rr < 4; rr++) {
                int d = w + 8 * rr;
                __stcs(&out_interp[(size_t)(b * DD + d) * NN + u0 + it * 32 + lane],
                       tile[it * 32 + lane][d]);
            }
        }
    }
}

extern "C" void kernel_launch(void* const* d_in, const int* in_sizes, int n_in,
                              void* d_out, int out_size) {
    const float* xyz         = (const float*)d_in[0];   // [B,N,3]
    const int*   neigh_idx   = (const int*)  d_in[1];   // [B,N,K]
    const float* feat_pool   = (const float*)d_in[2];   // [B,32,N,1]
    const int*   pool_idx    = (const int*)  d_in[3];   // [B,Np,K]
    const float* feat_interp = (const float*)d_in[4];   // [B,32,Np,1]
    const int*   interp_idx  = (const int*)  d_in[5];   // [B,N,1]

    float* out = (float*)d_out;
    float* out_rel    = out;                                // B*N*K*10
    float* out_pool   = out + (size_t)B * NN * KK * 10;     // B*32*Np
    float* out_interp = out_pool + (size_t)B * DD * NP;     // B*32*N

    // one-time side stream + events (host-side objects; no device allocs)
    static cudaStream_t s2 = nullptr;
    static cudaEvent_t evFork = nullptr, evJoin = nullptr;
    if (s2 == nullptr) {
        cudaStreamCreateWithFlags(&s2, cudaStreamNonBlocking);
        cudaEventCreateWithFlags(&evFork, cudaEventDisableTiming);
        cudaEventCreateWithFlags(&evJoin, cudaEventDisableTiming);
    }

    // fork: branch B (transposes -> pool/interp) runs parallel to branch A
    cudaEventRecord(evFork, 0);
    cudaStreamWaitEvent(s2, evFork, 0);

    // branch B on s2
    kT <<<TB1 + TB2, 256, 0, s2>>>(feat_pool, feat_interp);
    kPI<<<POOLB + IB4, 256, 0, s2>>>(pool_idx, interp_idx, out_pool, out_interp);
    cudaEventRecord(evJoin, s2);

    // branch A on default stream
    kX  <<<XB, 256>>>(xyz);
    kRel<<<RELB, 256>>>(neigh_idx, out_rel);

    // join
    cudaStreamWaitEvent(0, evJoin, 0);
}